// round 8
// baseline (speedup 1.0000x reference)
#include <cuda_runtime.h>
#include <cstdint>

#define TSEQ 2048
#define CH   2048
#define NH   16
#define HD   128

// Scratch (allocation-free rule: __device__ globals)
__device__ float g_q[TSEQ * CH];
__device__ float g_k[TSEQ * CH];
__device__ float g_v[TSEQ * CH];
__device__ float g_o[TSEQ * CH];
// tf32-rounded, K-group-permuted operands
__device__ float g_xp[TSEQ * CH];
__device__ float g_wqp[CH * CH];
__device__ float g_wkp[CH * CH];
__device__ float g_wvp[CH * CH];
__device__ float g_wop[CH * CH];
__device__ float g_op[TSEQ * CH];

// ===========================================================================
// helpers
// ===========================================================================
__device__ __forceinline__ uint32_t smem_to_u32(const void* p) {
    uint32_t a;
    asm("{ .reg .u64 t; cvta.to.shared.u64 t, %1; cvt.u32.u64 %0, t; }"
        : "=r"(a) : "l"(p));
    return a;
}

__device__ __forceinline__ void cp_async16(uint32_t dst, const void* src) {
    asm volatile("cp.async.cg.shared.global [%0], [%1], 16;"
                 :: "r"(dst), "l"(src) : "memory");
}
#define CP_COMMIT() asm volatile("cp.async.commit_group;" ::: "memory")
#define CP_WAIT0()  asm volatile("cp.async.wait_group 0;" ::: "memory")

__device__ __forceinline__ uint32_t f2tf32(float x) {
    uint32_t r;
    asm("cvt.rna.tf32.f32 %0, %1;" : "=r"(r) : "f"(x));
    return r;
}
__device__ __forceinline__ float tf32r(float x) {
    return __uint_as_float(f2tf32(x));
}

// D = A @ B + C, m16n8k8 tf32, row.col
__device__ __forceinline__ void mma_tf32(float* d, const uint32_t* a,
                                         const uint32_t* b, const float* c) {
    asm volatile(
        "mma.sync.aligned.m16n8k8.row.col.f32.tf32.tf32.f32 "
        "{%0,%1,%2,%3}, {%4,%5,%6,%7}, {%8,%9}, {%10,%11,%12,%13};"
        : "=f"(d[0]), "=f"(d[1]), "=f"(d[2]), "=f"(d[3])
        : "r"(a[0]), "r"(a[1]), "r"(a[2]), "r"(a[3]),
          "r"(b[0]), "r"(b[1]),
          "f"(c[0]), "f"(c[1]), "f"(c[2]), "f"(c[3]));
}

// ===========================================================================
// round-to-tf32 + permute each 8-col K-group to [0,4,1,5,2,6,3,7]
// ===========================================================================
__global__ __launch_bounds__(256) void round_permute5(
    const float* __restrict__ s0, const float* __restrict__ s1,
    const float* __restrict__ s2, const float* __restrict__ s3,
    const float* __restrict__ s4,
    float* __restrict__ d0, float* __restrict__ d1, float* __restrict__ d2,
    float* __restrict__ d3, float* __restrict__ d4, int nmat) {
    const int i = blockIdx.x * blockDim.x + threadIdx.x;
    const int m = blockIdx.y;
    if (m >= nmat) return;
    const float* s = (m == 0) ? s0 : (m == 1) ? s1 : (m == 2) ? s2
                   : (m == 3) ? s3 : s4;
    float* d = (m == 0) ? d0 : (m == 1) ? d1 : (m == 2) ? d2
             : (m == 3) ? d3 : d4;
    float4 a = *(const float4*)(s + (size_t)i * 8);
    float4 b = *(const float4*)(s + (size_t)i * 8 + 4);
    float4 o0 = make_float4(tf32r(a.x), tf32r(b.x), tf32r(a.y), tf32r(b.y));
    float4 o1 = make_float4(tf32r(a.z), tf32r(b.z), tf32r(a.w), tf32r(b.w));
    *(float4*)(d + (size_t)i * 8)     = o0;
    *(float4*)(d + (size_t)i * 8 + 4) = o1;
}

// ===========================================================================
// C[M,N] = A[M,K] @ B[N,K]^T  (2048^3) via tf32 mma.sync (verified R7)
// ===========================================================================
#define BK    16
#define LDS_P 24
#define P2    12
#define NTIL  (CH / BK)
#define GEMM_DSMEM (2 * 128 * LDS_P * 4 * 2)

__global__ __launch_bounds__(256, 2) void mma_gemm_p(
    const float* __restrict__ A,
    const float* __restrict__ B0, const float* __restrict__ B1,
    const float* __restrict__ B2,
    float* __restrict__ C0, float* __restrict__ C1, float* __restrict__ C2) {
    extern __shared__ __align__(16) float gsm[];
    float* As = gsm;
    float* Bs = gsm + 2 * 128 * LDS_P;

    const float* B = (blockIdx.z == 0) ? B0 : (blockIdx.z == 1) ? B1 : B2;
    float*       C = (blockIdx.z == 0) ? C0 : (blockIdx.z == 1) ? C1 : C2;

    const int tid  = threadIdx.x;
    const int lane = tid & 31;
    const int wid  = tid >> 5;
    const int wm   = (wid & 1) * 64;
    const int wn   = (wid >> 1) * 32;

    const int m0 = blockIdx.y * 128;
    const int n0 = blockIdx.x * 128;
    const float* Ab = A + (size_t)m0 * CH;
    const float* Bb = B + (size_t)n0 * CH;

    const uint32_t sA0 = smem_to_u32(As);
    const uint32_t sB0 = smem_to_u32(Bs);

    const int r0c = tid >> 2;
    const int c4  = (tid & 3) << 2;

    float acc[4][4][4];
#pragma unroll
    for (int mt = 0; mt < 4; mt++)
#pragma unroll
        for (int nt = 0; nt < 4; nt++)
#pragma unroll
            for (int e = 0; e < 4; e++) acc[mt][nt][e] = 0.f;

#pragma unroll
    for (int i = 0; i < 2; i++) {
        int row = r0c + i * 64;
        uint32_t off = (uint32_t)(row * LDS_P + c4) * 4u;
        cp_async16(sA0 + off, Ab + (size_t)row * CH + c4);
        cp_async16(sB0 + off, Bb + (size_t)row * CH + c4);
    }
    CP_COMMIT();

    for (int kt = 0; kt < NTIL; kt++) {
        CP_WAIT0();
        __syncthreads();

        if (kt + 1 < NTIL) {
            const int nbuf = (kt + 1) & 1;
            const int kc   = (kt + 1) * BK;
            const uint32_t sAd = sA0 + (uint32_t)(nbuf * 128 * LDS_P * 4);
            const uint32_t sBd = sB0 + (uint32_t)(nbuf * 128 * LDS_P * 4);
#pragma unroll
            for (int i = 0; i < 2; i++) {
                int row = r0c + i * 64;
                uint32_t off = (uint32_t)(row * LDS_P + c4) * 4u;
                cp_async16(sAd + off, Ab + (size_t)row * CH + kc + c4);
                cp_async16(sBd + off, Bb + (size_t)row * CH + kc + c4);
            }
            CP_COMMIT();
        }

        const int buf = kt & 1;
        const float2* Asb = (const float2*)(As + buf * 128 * LDS_P);
        const float2* Bsb = (const float2*)(Bs + buf * 128 * LDS_P);
#pragma unroll
        for (int ks = 0; ks < 2; ks++) {
            const int jq = ks * 4 + (lane & 3);
            uint32_t af[4][4], bf[4][2];
#pragma unroll
            for (int mt = 0; mt < 4; mt++) {
                int r = wm + mt * 16 + (lane >> 2);
                float2 f0 = Asb[r * P2 + jq];
                float2 f1 = Asb[(r + 8) * P2 + jq];
                af[mt][0] = __float_as_uint(f0.x);
                af[mt][1] = __float_as_uint(f1.x);
                af[mt][2] = __float_as_uint(f0.y);
                af[mt][3] = __float_as_uint(f1.y);
            }
#pragma unroll
            for (int nt = 0; nt < 4; nt++) {
                int cidx = wn + nt * 8 + (lane >> 2);
                float2 f = Bsb[cidx * P2 + jq];
                bf[nt][0] = __float_as_uint(f.x);
                bf[nt][1] = __float_as_uint(f.y);
            }
#pragma unroll
            for (int mt = 0; mt < 4; mt++)
#pragma unroll
                for (int nt = 0; nt < 4; nt++)
                    mma_tf32(acc[mt][nt], af[mt], bf[nt], acc[mt][nt]);
        }
        __syncthreads();
    }

#pragma unroll
    for (int mt = 0; mt < 4; mt++) {
        int r = m0 + wm + mt * 16 + (lane >> 2);
#pragma unroll
        for (int nt = 0; nt < 4; nt++) {
            int cidx = n0 + wn + nt * 8 + 2 * (lane & 3);
            *(float2*)(C + (size_t)r * CH + cidx) =
                make_float2(acc[mt][nt][0], acc[mt][nt][1]);
            *(float2*)(C + (size_t)(r + 8) * CH + cidx) =
                make_float2(acc[mt][nt][2], acc[mt][nt][3]);
        }
    }
}

// ---------------------------------------------------------------------------
// ReBased feature map (unchanged)
// ---------------------------------------------------------------------------
__global__ __launch_bounds__(256) void featmap(const float* __restrict__ gamma,
                                               const float* __restrict__ beta) {
    const int warp = threadIdx.x >> 5;
    const int lane = threadIdx.x & 31;
    const int row  = blockIdx.x * 8 + warp;
    float* base = (blockIdx.y == 0) ? g_q : g_k;
    const float scale = (blockIdx.y == 0) ? 0.08838834764831845f : 1.0f;
    const int t = row >> 4;
    const int h = row & 15;
    float* p = base + (size_t)t * CH + h * HD;

    float x[4];
    float s = 0.f, sq = 0.f;
#pragma unroll
    for (int r = 0; r < 4; r++) {
        int d = lane + 32 * r;
        float y = p[d] * gamma[d] + beta[d];
        x[r] = y;
        s  += y;
        sq += y * y;
    }
#pragma unroll
    for (int o = 16; o; o >>= 1) {
        s  += __shfl_xor_sync(0xFFFFFFFFu, s, o);
        sq += __shfl_xor_sync(0xFFFFFFFFu, sq, o);
    }
    const float mu  = s * (1.0f / HD);
    const float var = sq * (1.0f / HD) - mu * mu;
    const float rs  = rsqrtf(var + 1e-5f) * scale;
#pragma unroll
    for (int r = 0; r < 4; r++) p[lane + 32 * r] = (x[r] - mu) * rs;
}

// ===========================================================================
// Causal quadratic attention via tf32 mma.sync — 512 threads / 16 warps.
//   S = q.k^T 3-pass split-tf32; S2 = masked S^2 (stored tf32-rounded);
//   z rowsum (exact fp32); O += S2 @ V 1-pass tf32.
// QK warp tile 16x16 (4x4 warp grid), SV warp tile 16x32.
// Next k/v tile LDG-prefetched into registers, overlapped with mma phases.
// ===========================================================================
#define WQK 132
#define WVT 68
#define ATTN_SMEM2 (2 * 64 * WQK * 8 + 128 * WVT * 4 + 64 * WVT * 4 + 64 * 4)

__global__ __launch_bounds__(512, 1) void rebased_attn_mma() {
    extern __shared__ __align__(16) char dynsm[];
    float2* q_hl = (float2*)dynsm;                 // [64][WQK]
    float2* k_hl = q_hl + 64 * WQK;                // [64][WQK]
    float*  vt   = (float*)(k_hl + 64 * WQK);      // [128][WVT]
    float*  s2m  = vt + 128 * WVT;                 // [64][WVT]
    float*  zsh  = s2m + 64 * WVT;                 // [64]

    const int tid  = threadIdx.x;
    const int lane = tid & 31;
    const int wid  = tid >> 5;                     // 0..15
    const int qt   = 31 - blockIdx.x;              // heavy tiles first
    const int h    = blockIdx.y;
    const int q0   = qt * 64;

    const int wmQ = (wid & 3) * 16, wnQ = (wid >> 2) * 16;  // QK 16x16
    const int wmO = (wid & 3) * 16, wnO = (wid >> 2) * 32;  // SV 16x32

    // load slices: 16 floats per thread
    const int row = tid >> 3;            // 0..63
    const int cb  = (tid & 7) * 16;      // col base (4 float4)
    const int vj  = tid & 63;            // v: j index
    const int vdb = (tid >> 6) * 16;     // v: d base

    // ---- load q tile, split hi/lo ----
    {
        const float* src = g_q + (size_t)(q0 + row) * CH + h * HD + cb;
        float2* dst = q_hl + row * WQK + cb;
#pragma unroll
        for (int c = 0; c < 4; c++) {
            float4 x = *(const float4*)(src + c * 4);
            float xs[4] = {x.x, x.y, x.z, x.w};
#pragma unroll
            for (int i = 0; i < 4; i++) {
                float hi = tf32r(xs[i]);
                float lo = tf32r(xs[i] - hi);
                dst[c * 4 + i] = make_float2(hi, lo);
            }
        }
    }
    if (tid < 64) zsh[tid] = 0.f;

    float oacc[4][4];
#pragma unroll
    for (int nt = 0; nt < 4; nt++)
#pragma unroll
        for (int e = 0; e < 4; e++) oacc[nt][e] = 0.f;

    // ---- prefetch k/v tile 0 into registers ----
    float4 kr[4], vr[4];
    {
        const float* ks = g_k + (size_t)row * CH + h * HD + cb;
        const float* vs = g_v + (size_t)vj * CH + h * HD + vdb;
#pragma unroll
        for (int c = 0; c < 4; c++) kr[c] = *(const float4*)(ks + c * 4);
#pragma unroll
        for (int c = 0; c < 4; c++) vr[c] = *(const float4*)(vs + c * 4);
    }

    for (int kt = 0; kt <= qt; kt++) {
        __syncthreads();   // prev iter's k_hl/vt/s2m fully consumed

        // ---- store prefetched k (split) and v (transposed, rounded) ----
        {
            float2* kd = k_hl + row * WQK + cb;
#pragma unroll
            for (int c = 0; c < 4; c++) {
                float xs[4] = {kr[c].x, kr[c].y, kr[c].z, kr[c].w};
#pragma unroll
                for (int i = 0; i < 4; i++) {
                    float hi = tf32r(xs[i]);
                    float lo = tf32r(xs[i] - hi);
                    kd[c * 4 + i] = make_float2(hi, lo);
                }
            }
#pragma unroll
            for (int c = 0; c < 4; c++) {
                int d0 = vdb + c * 4;
                vt[(d0 + 0) * WVT + vj] = tf32r(vr[c].x);
                vt[(d0 + 1) * WVT + vj] = tf32r(vr[c].y);
                vt[(d0 + 2) * WVT + vj] = tf32r(vr[c].z);
                vt[(d0 + 3) * WVT + vj] = tf32r(vr[c].w);
            }
        }
        // ---- prefetch next tile (overlaps with mma phases below) ----
        if (kt < qt) {
            const int kn = (kt + 1) * 64;
            const float* ks = g_k + (size_t)(kn + row) * CH + h * HD + cb;
            const float* vs = g_v + (size_t)(kn + vj) * CH + h * HD + vdb;
#pragma unroll
            for (int c = 0; c < 4; c++) kr[c] = *(const float4*)(ks + c * 4);
#pragma unroll
            for (int c = 0; c < 4; c++) vr[c] = *(const float4*)(vs + c * 4);
        }
        __syncthreads();

        // ---- S = q.k^T, 3-pass split tf32 (warp tile 16x16) ----
        float sacc[2][4];
#pragma unroll
        for (int nt = 0; nt < 2; nt++)
#pragma unroll
            for (int e = 0; e < 4; e++) sacc[nt][e] = 0.f;

#pragma unroll 4
        for (int k8 = 0; k8 < 16; k8++) {
            const int kq = k8 * 8 + (lane & 3);
            const int r = wmQ + (lane >> 2);
            float2 a0 = q_hl[r * WQK + kq];
            float2 a1 = q_hl[(r + 8) * WQK + kq];
            float2 a2 = q_hl[r * WQK + kq + 4];
            float2 a3 = q_hl[(r + 8) * WQK + kq + 4];
            uint32_t ah[4] = {__float_as_uint(a0.x), __float_as_uint(a1.x),
                              __float_as_uint(a2.x), __float_as_uint(a3.x)};
            uint32_t al[4] = {__float_as_uint(a0.y), __float_as_uint(a1.y),
                              __float_as_uint(a2.y), __float_as_uint(a3.y)};
#pragma unroll
            for (int nt = 0; nt < 2; nt++) {
                int n = wnQ + nt * 8 + (lane >> 2);
                float2 b0 = k_hl[n * WQK + kq];
                float2 b1 = k_hl[n * WQK + kq + 4];
                uint32_t bh[2] = {__float_as_uint(b0.x), __float_as_uint(b1.x)};
                uint32_t bl[2] = {__float_as_uint(b0.y), __float_as_uint(b1.y)};
                mma_tf32(sacc[nt], ah, bh, sacc[nt]);
                mma_tf32(sacc[nt], ah, bl, sacc[nt]);
                mma_tf32(sacc[nt], al, bh, sacc[nt]);
            }
        }

        // ---- square, mask, store tf32-rounded s2, accumulate exact z ----
        const bool diag = (kt == qt);
        {
            const int r0l = wmQ + (lane >> 2);
            float zp0 = 0.f, zp1 = 0.f;
#pragma unroll
            for (int nt = 0; nt < 2; nt++) {
                const int c0l = wnQ + nt * 8 + 2 * (lane & 3);
                float s0 = sacc[nt][0]; s0 *= s0;
                float s1 = sacc[nt][1]; s1 *= s1;
                float s2 = sacc[nt][2]; s2 *= s2;
                float s3 = sacc[nt][3]; s3 *= s3;
                if (diag) {
                    if (c0l > r0l)         s0 = 0.f;
                    if (c0l + 1 > r0l)     s1 = 0.f;
                    if (c0l > r0l + 8)     s2 = 0.f;
                    if (c0l + 1 > r0l + 8) s3 = 0.f;
                }
                *(float2*)&s2m[r0l * WVT + c0l] =
                    make_float2(tf32r(s0), tf32r(s1));
                *(float2*)&s2m[(r0l + 8) * WVT + c0l] =
                    make_float2(tf32r(s2), tf32r(s3));
                zp0 += s0 + s1;
                zp1 += s2 + s3;
            }
            atomicAdd(&zsh[r0l], zp0);
            atomicAdd(&zsh[r0l + 8], zp1);
        }
        __syncthreads();

        // ---- O += S2 @ V (1-pass tf32, warp tile 16x32, no cvt) ----
#pragma unroll 2
        for (int k8 = 0; k8 < 8; k8++) {
            const int kq = k8 * 8 + (lane & 3);
            const int r = wmO + (lane >> 2);
            uint32_t a[4];
            a[0] = __float_as_uint(s2m[r * WVT + kq]);
            a[1] = __float_as_uint(s2m[(r + 8) * WVT + kq]);
            a[2] = __float_as_uint(s2m[r * WVT + kq + 4]);
            a[3] = __float_as_uint(s2m[(r + 8) * WVT + kq + 4]);
#pragma unroll
            for (int nt = 0; nt < 4; nt++) {
                int n = wnO + nt * 8 + (lane >> 2);
                uint32_t b[2];
                b[0] = __float_as_uint(vt[n * WVT + kq]);
                b[1] = __float_as_uint(vt[n * WVT + kq + 4]);
                mma_tf32(oacc[nt], a, b, oacc[nt]);
            }
        }
    }
    __syncthreads();   // final z atomics visible

    // ---- epilogue: divide by (z + eps), store ----
    {
        const int rl = wmO + (lane >> 2);
        const float inv0 = 1.0f / (zsh[rl] + 1e-5f);
        const float inv1 = 1.0f / (zsh[rl + 8] + 1e-5f);
        float* o0 = g_o + (size_t)(q0 + rl) * CH + h * HD;
        float* o1 = g_o + (size_t)(q0 + rl + 8) * CH + h * HD;
#pragma unroll
        for (int nt = 0; nt < 4; nt++) {
            const int cl = wnO + nt * 8 + 2 * (lane & 3);
            *(float2*)(o0 + cl) = make_float2(oacc[nt][0] * inv0,
                                              oacc[nt][1] * inv0);
            *(float2*)(o1 + cl) = make_float2(oacc[nt][2] * inv1,
                                              oacc[nt][3] * inv1);
        }
    }
}

// ---------------------------------------------------------------------------
extern "C" void kernel_launch(void* const* d_in, const int* in_sizes, int n_in,
                              void* d_out, int out_size) {
    const float* X     = (const float*)d_in[0];
    const float* Wq    = (const float*)d_in[1];
    const float* Wk    = (const float*)d_in[2];
    const float* Wv    = (const float*)d_in[3];
    const float* Wo    = (const float*)d_in[4];
    const float* gamma = (const float*)d_in[5];
    const float* beta  = (const float*)d_in[6];
    float* out = (float*)d_out;

    float *q, *k, *v, *o, *xp, *wqp, *wkp, *wvp, *wop, *op;
    cudaGetSymbolAddress((void**)&q, g_q);
    cudaGetSymbolAddress((void**)&k, g_k);
    cudaGetSymbolAddress((void**)&v, g_v);
    cudaGetSymbolAddress((void**)&o, g_o);
    cudaGetSymbolAddress((void**)&xp, g_xp);
    cudaGetSymbolAddress((void**)&wqp, g_wqp);
    cudaGetSymbolAddress((void**)&wkp, g_wkp);
    cudaGetSymbolAddress((void**)&wvp, g_wvp);
    cudaGetSymbolAddress((void**)&wop, g_wop);
    cudaGetSymbolAddress((void**)&op, g_op);

    cudaFuncSetAttribute(rebased_attn_mma,
                         cudaFuncAttributeMaxDynamicSharedMemorySize, ATTN_SMEM2);
    cudaFuncSetAttribute(mma_gemm_p,
                         cudaFuncAttributeMaxDynamicSharedMemorySize, GEMM_DSMEM);

    dim3 b256(256);
    const int NGRP = TSEQ * CH / 8;

    // pre-round + K-group permute: X, Wq, Wk, Wv, Wo
    round_permute5<<<dim3(NGRP / 256, 5), b256>>>(
        X, Wq, Wk, Wv, Wo, xp, wqp, wkp, wvp, wop, 5);

    // fused Q/K/V projections
    mma_gemm_p<<<dim3(16, 16, 3), b256, GEMM_DSMEM>>>(
        xp, wqp, wkp, wvp, q, k, v);

    // feature map (q scaled by D^-0.5, k unscaled)
    featmap<<<dim3(TSEQ * NH / 8, 2), b256>>>(gamma, beta);

    // causal quadratic attention (tf32 mma, split-tf32 scores, 512 thr)
    rebased_attn_mma<<<dim3(TSEQ / 64, NH), dim3(512), ATTN_SMEM2>>>();

    // round+permute attention output, then O projection
    round_permute5<<<dim3(NGRP / 256, 1), b256>>>(
        o, o, o, o, o, op, op, op, op, op, 1);
    mma_gemm_p<<<dim3(16, 16, 1), b256, GEMM_DSMEM>>>(
        op, wop, wop, wop, out, out, out);
}

// round 9
// speedup vs baseline: 1.2979x; 1.2979x over previous
#include <cuda_runtime.h>
#include <cstdint>

#define TSEQ 2048
#define CH   2048
#define NH   16
#define HD   128

// Scratch (allocation-free rule: __device__ globals)
__device__ float g_q[TSEQ * CH];
__device__ float g_k[TSEQ * CH];
__device__ float g_v[TSEQ * CH];
__device__ float g_o[TSEQ * CH];
// tf32-rounded, K-group-permuted operands
__device__ float g_xp[TSEQ * CH];
__device__ float g_wqp[CH * CH];
__device__ float g_wkp[CH * CH];
__device__ float g_wvp[CH * CH];
__device__ float g_wop[CH * CH];
__device__ float g_op[TSEQ * CH];

// ===========================================================================
// helpers
// ===========================================================================
__device__ __forceinline__ uint32_t smem_to_u32(const void* p) {
    uint32_t a;
    asm("{ .reg .u64 t; cvta.to.shared.u64 t, %1; cvt.u32.u64 %0, t; }"
        : "=r"(a) : "l"(p));
    return a;
}

__device__ __forceinline__ void cp_async16(uint32_t dst, const void* src) {
    asm volatile("cp.async.cg.shared.global [%0], [%1], 16;"
                 :: "r"(dst), "l"(src) : "memory");
}
#define CP_COMMIT() asm volatile("cp.async.commit_group;" ::: "memory")
#define CP_WAIT0()  asm volatile("cp.async.wait_group 0;" ::: "memory")
#define CP_WAIT1()  asm volatile("cp.async.wait_group 1;" ::: "memory")

__device__ __forceinline__ uint32_t f2tf32(float x) {
    uint32_t r;
    asm("cvt.rna.tf32.f32 %0, %1;" : "=r"(r) : "f"(x));
    return r;
}
__device__ __forceinline__ float tf32r(float x) {
    return __uint_as_float(f2tf32(x));
}

// D = A @ B + C, m16n8k8 tf32, row.col
__device__ __forceinline__ void mma_tf32(float* d, const uint32_t* a,
                                         const uint32_t* b, const float* c) {
    asm volatile(
        "mma.sync.aligned.m16n8k8.row.col.f32.tf32.tf32.f32 "
        "{%0,%1,%2,%3}, {%4,%5,%6,%7}, {%8,%9}, {%10,%11,%12,%13};"
        : "=f"(d[0]), "=f"(d[1]), "=f"(d[2]), "=f"(d[3])
        : "r"(a[0]), "r"(a[1]), "r"(a[2]), "r"(a[3]),
          "r"(b[0]), "r"(b[1]),
          "f"(c[0]), "f"(c[1]), "f"(c[2]), "f"(c[3]));
}

// ===========================================================================
// round-to-tf32 + permute each 8-col K-group to [0,4,1,5,2,6,3,7]
// ===========================================================================
__global__ __launch_bounds__(256) void round_permute5(
    const float* __restrict__ s0, const float* __restrict__ s1,
    const float* __restrict__ s2, const float* __restrict__ s3,
    const float* __restrict__ s4,
    float* __restrict__ d0, float* __restrict__ d1, float* __restrict__ d2,
    float* __restrict__ d3, float* __restrict__ d4, int nmat) {
    const int i = blockIdx.x * blockDim.x + threadIdx.x;
    const int m = blockIdx.y;
    if (m >= nmat) return;
    const float* s = (m == 0) ? s0 : (m == 1) ? s1 : (m == 2) ? s2
                   : (m == 3) ? s3 : s4;
    float* d = (m == 0) ? d0 : (m == 1) ? d1 : (m == 2) ? d2
             : (m == 3) ? d3 : d4;
    float4 a = *(const float4*)(s + (size_t)i * 8);
    float4 b = *(const float4*)(s + (size_t)i * 8 + 4);
    float4 o0 = make_float4(tf32r(a.x), tf32r(b.x), tf32r(a.y), tf32r(b.y));
    float4 o1 = make_float4(tf32r(a.z), tf32r(b.z), tf32r(a.w), tf32r(b.w));
    *(float4*)(d + (size_t)i * 8)     = o0;
    *(float4*)(d + (size_t)i * 8 + 4) = o1;
}

// ===========================================================================
// C[M,N] = A[M,K] @ B[N,K]^T  (2048^3) via tf32 mma.sync (verified R7)
// ===========================================================================
#define BK    16
#define LDS_P 24
#define P2    12
#define NTIL  (CH / BK)
#define GEMM_DSMEM (2 * 128 * LDS_P * 4 * 2)

__global__ __launch_bounds__(256, 2) void mma_gemm_p(
    const float* __restrict__ A,
    const float* __restrict__ B0, const float* __restrict__ B1,
    const float* __restrict__ B2,
    float* __restrict__ C0, float* __restrict__ C1, float* __restrict__ C2) {
    extern __shared__ __align__(16) float gsm[];
    float* As = gsm;
    float* Bs = gsm + 2 * 128 * LDS_P;

    const float* B = (blockIdx.z == 0) ? B0 : (blockIdx.z == 1) ? B1 : B2;
    float*       C = (blockIdx.z == 0) ? C0 : (blockIdx.z == 1) ? C1 : C2;

    const int tid  = threadIdx.x;
    const int lane = tid & 31;
    const int wid  = tid >> 5;
    const int wm   = (wid & 1) * 64;
    const int wn   = (wid >> 1) * 32;

    const int m0 = blockIdx.y * 128;
    const int n0 = blockIdx.x * 128;
    const float* Ab = A + (size_t)m0 * CH;
    const float* Bb = B + (size_t)n0 * CH;

    const uint32_t sA0 = smem_to_u32(As);
    const uint32_t sB0 = smem_to_u32(Bs);

    const int r0c = tid >> 2;
    const int c4  = (tid & 3) << 2;

    float acc[4][4][4];
#pragma unroll
    for (int mt = 0; mt < 4; mt++)
#pragma unroll
        for (int nt = 0; nt < 4; nt++)
#pragma unroll
            for (int e = 0; e < 4; e++) acc[mt][nt][e] = 0.f;

#pragma unroll
    for (int i = 0; i < 2; i++) {
        int row = r0c + i * 64;
        uint32_t off = (uint32_t)(row * LDS_P + c4) * 4u;
        cp_async16(sA0 + off, Ab + (size_t)row * CH + c4);
        cp_async16(sB0 + off, Bb + (size_t)row * CH + c4);
    }
    CP_COMMIT();

    for (int kt = 0; kt < NTIL; kt++) {
        CP_WAIT0();
        __syncthreads();

        if (kt + 1 < NTIL) {
            const int nbuf = (kt + 1) & 1;
            const int kc   = (kt + 1) * BK;
            const uint32_t sAd = sA0 + (uint32_t)(nbuf * 128 * LDS_P * 4);
            const uint32_t sBd = sB0 + (uint32_t)(nbuf * 128 * LDS_P * 4);
#pragma unroll
            for (int i = 0; i < 2; i++) {
                int row = r0c + i * 64;
                uint32_t off = (uint32_t)(row * LDS_P + c4) * 4u;
                cp_async16(sAd + off, Ab + (size_t)row * CH + kc + c4);
                cp_async16(sBd + off, Bb + (size_t)row * CH + kc + c4);
            }
            CP_COMMIT();
        }

        const int buf = kt & 1;
        const float2* Asb = (const float2*)(As + buf * 128 * LDS_P);
        const float2* Bsb = (const float2*)(Bs + buf * 128 * LDS_P);
#pragma unroll
        for (int ks = 0; ks < 2; ks++) {
            const int jq = ks * 4 + (lane & 3);
            uint32_t af[4][4], bf[4][2];
#pragma unroll
            for (int mt = 0; mt < 4; mt++) {
                int r = wm + mt * 16 + (lane >> 2);
                float2 f0 = Asb[r * P2 + jq];
                float2 f1 = Asb[(r + 8) * P2 + jq];
                af[mt][0] = __float_as_uint(f0.x);
                af[mt][1] = __float_as_uint(f1.x);
                af[mt][2] = __float_as_uint(f0.y);
                af[mt][3] = __float_as_uint(f1.y);
            }
#pragma unroll
            for (int nt = 0; nt < 4; nt++) {
                int cidx = wn + nt * 8 + (lane >> 2);
                float2 f = Bsb[cidx * P2 + jq];
                bf[nt][0] = __float_as_uint(f.x);
                bf[nt][1] = __float_as_uint(f.y);
            }
#pragma unroll
            for (int mt = 0; mt < 4; mt++)
#pragma unroll
                for (int nt = 0; nt < 4; nt++)
                    mma_tf32(acc[mt][nt], af[mt], bf[nt], acc[mt][nt]);
        }
        __syncthreads();
    }

#pragma unroll
    for (int mt = 0; mt < 4; mt++) {
        int r = m0 + wm + mt * 16 + (lane >> 2);
#pragma unroll
        for (int nt = 0; nt < 4; nt++) {
            int cidx = n0 + wn + nt * 8 + 2 * (lane & 3);
            *(float2*)(C + (size_t)r * CH + cidx) =
                make_float2(acc[mt][nt][0], acc[mt][nt][1]);
            *(float2*)(C + (size_t)(r + 8) * CH + cidx) =
                make_float2(acc[mt][nt][2], acc[mt][nt][3]);
        }
    }
}

// ---------------------------------------------------------------------------
// ReBased feature map (unchanged)
// ---------------------------------------------------------------------------
__global__ __launch_bounds__(256) void featmap(const float* __restrict__ gamma,
                                               const float* __restrict__ beta) {
    const int warp = threadIdx.x >> 5;
    const int lane = threadIdx.x & 31;
    const int row  = blockIdx.x * 8 + warp;
    float* base = (blockIdx.y == 0) ? g_q : g_k;
    const float scale = (blockIdx.y == 0) ? 0.08838834764831845f : 1.0f;
    const int t = row >> 4;
    const int h = row & 15;
    float* p = base + (size_t)t * CH + h * HD;

    float x[4];
    float s = 0.f, sq = 0.f;
#pragma unroll
    for (int r = 0; r < 4; r++) {
        int d = lane + 32 * r;
        float y = p[d] * gamma[d] + beta[d];
        x[r] = y;
        s  += y;
        sq += y * y;
    }
#pragma unroll
    for (int o = 16; o; o >>= 1) {
        s  += __shfl_xor_sync(0xFFFFFFFFu, s, o);
        sq += __shfl_xor_sync(0xFFFFFFFFu, sq, o);
    }
    const float mu  = s * (1.0f / HD);
    const float var = sq * (1.0f / HD) - mu * mu;
    const float rs  = rsqrtf(var + 1e-5f) * scale;
#pragma unroll
    for (int r = 0; r < 4; r++) p[lane + 32 * r] = (x[r] - mu) * rs;
}

// ===========================================================================
// Causal quadratic attention v3 — 256 thr / 8 warps (R7 frame):
//   S = q.k^T, 1-PASS tf32 (cvt.rna at fragment load; rounding errors in the
//   weights cancel in O = sum(w v)/(sum(w)+eps) since z sums the SAME rounded
//   w values as the numerator).
//   k tiles: cp.async double-buffered. v tiles: register-prefetched LDG,
//   stored transposed + tf32-rounded. 2 barriers per k-tile.
// QK warp tile 32x16 (grid 2x4), SV warp tile 32x32 (grid 2x4).
// smem: qs[64][132] | ks[2][64][132] | vt[2][128][68] | s2m[64][68] | z[64]
// ===========================================================================
#define WQ 132
#define WV 68
#define ATTN_SMEM3 ((64 * WQ + 2 * 64 * WQ + 2 * 128 * WV + 64 * WV + 64) * 4)

__global__ __launch_bounds__(256, 1) void rebased_attn_mma() {
    extern __shared__ __align__(16) float asm_[];
    float* qs  = asm_;                      // [64][WQ]
    float* ks  = qs + 64 * WQ;              // [2][64][WQ]
    float* vt  = ks + 2 * 64 * WQ;          // [2][128][WV]
    float* s2m = vt + 2 * 128 * WV;         // [64][WV]
    float* zsh = s2m + 64 * WV;             // [64]

    const int tid  = threadIdx.x;
    const int lane = tid & 31;
    const int wid  = tid >> 5;
    const int qt   = 31 - blockIdx.x;       // heavy tiles first
    const int h    = blockIdx.y;
    const int q0   = qt * 64;

    const int wmQ = (wid & 1) * 32, wnQ = (wid >> 1) * 16;  // QK 32x16
    const int wmO = (wid & 1) * 32, wnO = (wid >> 1) * 32;  // SV 32x32

    const uint32_t qs_u = smem_to_u32(qs);
    const uint32_t ks_u = smem_to_u32(ks);

    // v load slice (R7 mapping): 32 floats per thread
    const int vj  = tid & 63;
    const int vdb = (tid >> 6) * 4;

    // ---- prologue: cp.async q tile + k tile 0 (one group) ----
#pragma unroll
    for (int i = 0; i < 8; i++) {
        const int row = wid + 8 * i;
        const uint32_t so = (uint32_t)(row * WQ + lane * 4) * 4u;
        cp_async16(qs_u + so, g_q + (size_t)(q0 + row) * CH + h * HD + lane * 4);
        cp_async16(ks_u + so, g_k + (size_t)row * CH + h * HD + lane * 4);
    }
    CP_COMMIT();

    // prefetch v tile 0 into registers
    float4 vr[8];
    {
        const float* vs = g_v + (size_t)vj * CH + h * HD;
#pragma unroll
        for (int c = 0; c < 8; c++) vr[c] = *(const float4*)(vs + vdb + c * 16);
    }
    if (tid < 64) zsh[tid] = 0.f;

    float oacc[2][4][4];
#pragma unroll
    for (int mt = 0; mt < 2; mt++)
#pragma unroll
        for (int nt = 0; nt < 4; nt++)
#pragma unroll
            for (int e = 0; e < 4; e++) oacc[mt][nt][e] = 0.f;

    for (int kt = 0; kt <= qt; kt++) {
        const int buf = kt & 1;

        // issue cp.async for k tile kt+1 (other buffer)
        if (kt < qt) {
            const int kn = (kt + 1) * 64;
            const uint32_t kd = ks_u + (uint32_t)(((kt + 1) & 1) * 64 * WQ * 4);
#pragma unroll
            for (int i = 0; i < 8; i++) {
                const int row = wid + 8 * i;
                cp_async16(kd + (uint32_t)(row * WQ + lane * 4) * 4u,
                           g_k + (size_t)(kn + row) * CH + h * HD + lane * 4);
            }
            CP_COMMIT();
        }

        // store prefetched v (transposed, tf32-rounded) into vt[buf]
        {
            float* vtb = vt + buf * 128 * WV;
#pragma unroll
            for (int c = 0; c < 8; c++) {
                const int d0 = vdb + c * 16;
                vtb[(d0 + 0) * WV + vj] = tf32r(vr[c].x);
                vtb[(d0 + 1) * WV + vj] = tf32r(vr[c].y);
                vtb[(d0 + 2) * WV + vj] = tf32r(vr[c].z);
                vtb[(d0 + 3) * WV + vj] = tf32r(vr[c].w);
            }
        }
        // prefetch v tile kt+1
        if (kt < qt) {
            const float* vs = g_v + (size_t)((kt + 1) * 64 + vj) * CH + h * HD;
#pragma unroll
            for (int c = 0; c < 8; c++)
                vr[c] = *(const float4*)(vs + vdb + c * 16);
        }

        if (kt < qt) { CP_WAIT1(); } else { CP_WAIT0(); }
        __syncthreads();   // ks[buf] + vt[buf] ready; s2m free

        // ---- S = q.k^T, 1-pass tf32 ----
        const float* ksb = ks + buf * 64 * WQ;
        float sacc[2][2][4];
#pragma unroll
        for (int mt = 0; mt < 2; mt++)
#pragma unroll
            for (int nt = 0; nt < 2; nt++)
#pragma unroll
                for (int e = 0; e < 4; e++) sacc[mt][nt][e] = 0.f;

#pragma unroll 4
        for (int k8 = 0; k8 < 16; k8++) {
            const int kq = k8 * 8 + (lane & 3);
            uint32_t af[2][4], bf[2][2];
#pragma unroll
            for (int mt = 0; mt < 2; mt++) {
                const int r = wmQ + mt * 16 + (lane >> 2);
                af[mt][0] = f2tf32(qs[r * WQ + kq]);
                af[mt][1] = f2tf32(qs[(r + 8) * WQ + kq]);
                af[mt][2] = f2tf32(qs[r * WQ + kq + 4]);
                af[mt][3] = f2tf32(qs[(r + 8) * WQ + kq + 4]);
            }
#pragma unroll
            for (int nt = 0; nt < 2; nt++) {
                const int n = wnQ + nt * 8 + (lane >> 2);
                bf[nt][0] = f2tf32(ksb[n * WQ + kq]);
                bf[nt][1] = f2tf32(ksb[n * WQ + kq + 4]);
            }
#pragma unroll
            for (int mt = 0; mt < 2; mt++)
#pragma unroll
                for (int nt = 0; nt < 2; nt++)
                    mma_tf32(sacc[mt][nt], af[mt], bf[nt], sacc[mt][nt]);
        }

        // ---- square, mask, store tf32-rounded; z sums the SAME values ----
        const bool diag = (kt == qt);
#pragma unroll
        for (int mt = 0; mt < 2; mt++) {
            const int r0l = wmQ + mt * 16 + (lane >> 2);
            float zp0 = 0.f, zp1 = 0.f;
#pragma unroll
            for (int nt = 0; nt < 2; nt++) {
                const int c0l = wnQ + nt * 8 + 2 * (lane & 3);
                float s0 = sacc[mt][nt][0]; s0 *= s0;
                float s1 = sacc[mt][nt][1]; s1 *= s1;
                float s2 = sacc[mt][nt][2]; s2 *= s2;
                float s3 = sacc[mt][nt][3]; s3 *= s3;
                if (diag) {
                    if (c0l > r0l)         s0 = 0.f;
                    if (c0l + 1 > r0l)     s1 = 0.f;
                    if (c0l > r0l + 8)     s2 = 0.f;
                    if (c0l + 1 > r0l + 8) s3 = 0.f;
                }
                s0 = tf32r(s0); s1 = tf32r(s1); s2 = tf32r(s2); s3 = tf32r(s3);
                *(float2*)&s2m[r0l * WV + c0l]       = make_float2(s0, s1);
                *(float2*)&s2m[(r0l + 8) * WV + c0l] = make_float2(s2, s3);
                zp0 += s0 + s1;
                zp1 += s2 + s3;
            }
            atomicAdd(&zsh[r0l], zp0);
            atomicAdd(&zsh[r0l + 8], zp1);
        }
        __syncthreads();

        // ---- O += S2 @ V (1-pass tf32; operands pre-rounded, no cvt) ----
        const float* vtb = vt + buf * 128 * WV;
#pragma unroll 2
        for (int k8 = 0; k8 < 8; k8++) {
            const int kq = k8 * 8 + (lane & 3);
            uint32_t a[2][4];
#pragma unroll
            for (int mt = 0; mt < 2; mt++) {
                const int r = wmO + mt * 16 + (lane >> 2);
                a[mt][0] = __float_as_uint(s2m[r * WV + kq]);
                a[mt][1] = __float_as_uint(s2m[(r + 8) * WV + kq]);
                a[mt][2] = __float_as_uint(s2m[r * WV + kq + 4]);
                a[mt][3] = __float_as_uint(s2m[(r + 8) * WV + kq + 4]);
            }
#pragma unroll
            for (int nt = 0; nt < 4; nt++) {
                const int n = wnO + nt * 8 + (lane >> 2);
                uint32_t b[2];
                b[0] = __float_as_uint(vtb[n * WV + kq]);
                b[1] = __float_as_uint(vtb[n * WV + kq + 4]);
#pragma unroll
                for (int mt = 0; mt < 2; mt++)
                    mma_tf32(oacc[mt][nt], a[mt], b, oacc[mt][nt]);
            }
        }
    }

    // ---- epilogue: divide by (z + eps), store ----
    // (z atomics completed before the last pre-SV barrier)
#pragma unroll
    for (int mt = 0; mt < 2; mt++) {
        const int rl = wmO + mt * 16 + (lane >> 2);
        const float inv0 = 1.0f / (zsh[rl] + 1e-5f);
        const float inv1 = 1.0f / (zsh[rl + 8] + 1e-5f);
        float* o0 = g_o + (size_t)(q0 + rl) * CH + h * HD;
        float* o1 = g_o + (size_t)(q0 + rl + 8) * CH + h * HD;
#pragma unroll
        for (int nt = 0; nt < 4; nt++) {
            const int cl = wnO + nt * 8 + 2 * (lane & 3);
            *(float2*)(o0 + cl) = make_float2(oacc[mt][nt][0] * inv0,
                                              oacc[mt][nt][1] * inv0);
            *(float2*)(o1 + cl) = make_float2(oacc[mt][nt][2] * inv1,
                                              oacc[mt][nt][3] * inv1);
        }
    }
}

// ---------------------------------------------------------------------------
extern "C" void kernel_launch(void* const* d_in, const int* in_sizes, int n_in,
                              void* d_out, int out_size) {
    const float* X     = (const float*)d_in[0];
    const float* Wq    = (const float*)d_in[1];
    const float* Wk    = (const float*)d_in[2];
    const float* Wv    = (const float*)d_in[3];
    const float* Wo    = (const float*)d_in[4];
    const float* gamma = (const float*)d_in[5];
    const float* beta  = (const float*)d_in[6];
    float* out = (float*)d_out;

    float *q, *k, *v, *o, *xp, *wqp, *wkp, *wvp, *wop, *op;
    cudaGetSymbolAddress((void**)&q, g_q);
    cudaGetSymbolAddress((void**)&k, g_k);
    cudaGetSymbolAddress((void**)&v, g_v);
    cudaGetSymbolAddress((void**)&o, g_o);
    cudaGetSymbolAddress((void**)&xp, g_xp);
    cudaGetSymbolAddress((void**)&wqp, g_wqp);
    cudaGetSymbolAddress((void**)&wkp, g_wkp);
    cudaGetSymbolAddress((void**)&wvp, g_wvp);
    cudaGetSymbolAddress((void**)&wop, g_wop);
    cudaGetSymbolAddress((void**)&op, g_op);

    cudaFuncSetAttribute(rebased_attn_mma,
                         cudaFuncAttributeMaxDynamicSharedMemorySize, ATTN_SMEM3);
    cudaFuncSetAttribute(mma_gemm_p,
                         cudaFuncAttributeMaxDynamicSharedMemorySize, GEMM_DSMEM);

    dim3 b256(256);
    const int NGRP = TSEQ * CH / 8;

    // pre-round + K-group permute: X, Wq, Wk, Wv, Wo
    round_permute5<<<dim3(NGRP / 256, 5), b256>>>(
        X, Wq, Wk, Wv, Wo, xp, wqp, wkp, wvp, wop, 5);

    // fused Q/K/V projections
    mma_gemm_p<<<dim3(16, 16, 3), b256, GEMM_DSMEM>>>(
        xp, wqp, wkp, wvp, q, k, v);

    // feature map (q scaled by D^-0.5, k unscaled)
    featmap<<<dim3(TSEQ * NH / 8, 2), b256>>>(gamma, beta);

    // causal quadratic attention (1-pass tf32 mma, cp.async k, 256 thr)
    rebased_attn_mma<<<dim3(TSEQ / 64, NH), b256, ATTN_SMEM3>>>();

    // round+permute attention output, then O projection
    round_permute5<<<dim3(NGRP / 256, 1), b256>>>(
        o, o, o, o, o, op, op, op, op, op, 1);
    mma_gemm_p<<<dim3(16, 16, 1), b256, GEMM_DSMEM>>>(
        op, wop, wop, wop, out, out, out);
}